// round 3
// baseline (speedup 1.0000x reference)
#include <cuda_runtime.h>

#define RL  132     // padded smem row length (floats)
#define NP  128     // particles per event
#define UN  128     // hidden units
#define NHID 6
#define NTHREADS 256

// smem layout (floats):
//   Xs  [128][RL]  : xT (unit-major activations)   (also transpose staging early)
//   Ys  [128][RL]  : y  (particle-major dense out) (also x0T early, partials late)
//   AD  [128][RL]  : adjT  (AD[n][i] = adj[i][n])
//   WS  [2][16][128] : W chunk double buffer
//   MSK [128], RED[8] (RED[7] = denom)
#define SMEM_FLOATS (3 * NP * RL + 2 * 16 * UN + NP + 8)
#define SMEM_BYTES  (SMEM_FLOATS * 4)

__device__ __forceinline__ unsigned long long ffma2(unsigned long long a,
                                                    unsigned long long b,
                                                    unsigned long long c) {
    unsigned long long d;
    asm("fma.rn.f32x2 %0, %1, %2, %3;" : "=l"(d) : "l"(a), "l"(b), "l"(c));
    return d;
}

__device__ __forceinline__ unsigned long long pack2(float x) {
    unsigned long long d;
    asm("mov.b64 %0, {%1, %1};" : "=l"(d) : "f"(x));
    return d;
}

__device__ __forceinline__ float2 unpack2(unsigned long long v) {
    float2 f;
    asm("mov.b64 {%0, %1}, %2;" : "=f"(f.x), "=f"(f.y) : "l"(v));
    return f;
}

// One k-step of the 8x8-per-thread microkernel, f32x2 packed along j.
// C[i][j] += As[k][i] * Bs[k][j]
__device__ __forceinline__ void mk_step(const float* __restrict__ As, int as,
                                        const float* __restrict__ Bs, int bs,
                                        int k, int i0, int j0,
                                        unsigned long long acc[8][4]) {
    float4 a0 = *(const float4*)(As + k * as + i0);
    float4 a1 = *(const float4*)(As + k * as + i0 + 4);
    ulonglong2 bq0 = *(const ulonglong2*)(Bs + k * bs + j0);
    ulonglong2 bq1 = *(const ulonglong2*)(Bs + k * bs + j0 + 4);
    unsigned long long bp[4] = {bq0.x, bq0.y, bq1.x, bq1.y};
    float av[8] = {a0.x, a0.y, a0.z, a0.w, a1.x, a1.y, a1.z, a1.w};
#pragma unroll
    for (int ii = 0; ii < 8; ++ii) {
        unsigned long long ap = pack2(av[ii]);
#pragma unroll
        for (int p = 0; p < 4; ++p) acc[ii][p] = ffma2(ap, bp[p], acc[ii][p]);
    }
}

__device__ __forceinline__ void zero_acc(unsigned long long acc[8][4]) {
#pragma unroll
    for (int ii = 0; ii < 8; ++ii)
#pragma unroll
        for (int p = 0; p < 4; ++p) acc[ii][p] = 0ull;
}

__global__ __launch_bounds__(NTHREADS, 1)
void gcn_fused_kernel(const int* __restrict__ pdg,
                      const float* __restrict__ feat,
                      const float* __restrict__ adj,
                      const float* __restrict__ mask,
                      const float* __restrict__ emb,
                      const float* __restrict__ W_in,
                      const float* __restrict__ b_in,
                      const float* __restrict__ W_h,
                      const float* __restrict__ b_h,
                      const float* __restrict__ W_out,
                      const float* __restrict__ b_out,
                      float* __restrict__ out)
{
    extern __shared__ float sm[];
    float* Xs  = sm;
    float* Ys  = Xs + NP * RL;
    float* AD  = Ys + NP * RL;
    float* WS  = AD + NP * RL;          // 2 * 16 * 128 floats
    float* MSK = WS + 2 * 16 * UN;      // 128
    float* RED = MSK + NP;              // 8 (RED[7] = denom)

    const int b    = blockIdx.x;
    const int tid  = threadIdx.x;
    const int lane = tid & 31;
    const int warp = tid >> 5;

    // thread tile mapping: 16x16 grid of 8x8 tiles; each warp = 4 ty x 8 tx
    const int ty = ((warp >> 1) << 2) + (lane >> 3);   // 0..15
    const int tx = ((warp & 1) << 3) + (lane & 7);     // 0..15
    const int i0 = ty << 3;
    const int j0 = tx << 3;

    const float* adjb = adj + (size_t)b * NP * NP;

    // ---------- Phase A: transpose adj into AD (AD[n][i] = adj[i][n]) ----------
    {
        float* stg = Xs + warp * (32 * 33);   // per-warp 32x33 staging
#pragma unroll
        for (int t2 = 0; t2 < 2; ++t2) {
            int t  = warp + t2 * 8;           // 16 tiles of 32x32
            int ti = t >> 2, tj = t & 3;
            // fill: coalesced global float4 read, SCALAR smem stores
            // (stride-33 rows are not 16B aligned for odd r; scalar stores are
            //  conflict-free here: bank = (d + 4*(c4+s) + q) mod 32 covers 0..31)
#pragma unroll
            for (int s = 0; s < 8; ++s) {
                int r  = s * 4 + (lane >> 3);
                int c4 = lane & 7;
                float4 v = *(const float4*)(adjb + (ti * 32 + r) * NP + tj * 32 + c4 * 4);
                float* d = stg + r * 33 + c4 * 4;
                d[0] = v.x; d[1] = v.y; d[2] = v.z; d[3] = v.w;
            }
            __syncwarp();
            // drain transposed: conflict-free (33-pad) LDS + scalar STS
#pragma unroll
            for (int n2 = 0; n2 < 32; ++n2) {
                AD[(tj * 32 + n2) * RL + ti * 32 + lane] = stg[lane * 33 + n2];
            }
            __syncwarp();
        }
    }

    // ---------- Phase B: x0T into Ys, W_in into WS, mask ----------
    if (tid < 128) {
        int n = tid;
        float4 f0 = *(const float4*)(feat + ((size_t)b * NP + n) * 8);
        float4 f1 = *(const float4*)(feat + ((size_t)b * NP + n) * 8 + 4);
        Ys[0 * RL + n] = f0.x; Ys[1 * RL + n] = f0.y;
        Ys[2 * RL + n] = f0.z; Ys[3 * RL + n] = f0.w;
        Ys[4 * RL + n] = f1.x; Ys[5 * RL + n] = f1.y;
        Ys[6 * RL + n] = f1.z; Ys[7 * RL + n] = f1.w;
        MSK[n] = mask[(size_t)b * NP + n];
    } else {
        int n = tid - 128;
        int p = pdg[(size_t)b * NP + n];
        float4 e0 = *(const float4*)(emb + p * 8);
        float4 e1 = *(const float4*)(emb + p * 8 + 4);
        Ys[ 8 * RL + n] = e0.x; Ys[ 9 * RL + n] = e0.y;
        Ys[10 * RL + n] = e0.z; Ys[11 * RL + n] = e0.w;
        Ys[12 * RL + n] = e1.x; Ys[13 * RL + n] = e1.y;
        Ys[14 * RL + n] = e1.z; Ys[15 * RL + n] = e1.w;
    }
    // W_in (16x128) into WS buf0
    *(float4*)(WS + tid * 4)        = *(const float4*)(W_in + tid * 4);
    *(float4*)(WS + 1024 + tid * 4) = *(const float4*)(W_in + 1024 + tid * 4);
    __syncthreads();

    // denom = max(sum(mask), 1)  (warp 0)
    if (warp == 0) {
        float s = MSK[lane] + MSK[lane + 32] + MSK[lane + 64] + MSK[lane + 96];
#pragma unroll
        for (int o = 16; o; o >>= 1) s += __shfl_down_sync(0xffffffffu, s, o);
        if (lane == 0) RED[7] = fmaxf(s, 1.0f);
    }

    unsigned long long acc[8][4];

    // ---------- Input GEMM: Xs[u][n] = sum_c W_in[c][u] * x0T[c][n] + b_in[u] ----------
    zero_acc(acc);
#pragma unroll 8
    for (int k = 0; k < 16; ++k)
        mk_step(WS, UN, Ys, RL, k, i0, j0, acc);
    {
        float4 bi0 = *(const float4*)(b_in + i0);
        float4 bi1 = *(const float4*)(b_in + i0 + 4);
        float bia[8] = {bi0.x, bi0.y, bi0.z, bi0.w, bi1.x, bi1.y, bi1.z, bi1.w};
#pragma unroll
        for (int ii = 0; ii < 8; ++ii) {
            float2 q0 = unpack2(acc[ii][0]);
            float2 q1 = unpack2(acc[ii][1]);
            float2 q2 = unpack2(acc[ii][2]);
            float2 q3 = unpack2(acc[ii][3]);
            float bb = bia[ii];
            float4 r0 = make_float4(q0.x + bb, q0.y + bb, q1.x + bb, q1.y + bb);
            float4 r1 = make_float4(q2.x + bb, q2.y + bb, q3.x + bb, q3.y + bb);
            *(float4*)(Xs + (i0 + ii) * RL + j0)     = r0;
            *(float4*)(Xs + (i0 + ii) * RL + j0 + 4) = r1;
        }
    }
    __syncthreads();

    // ---------- Hidden layers ----------
#pragma unroll 1
    for (int l = 0; l < NHID; ++l) {
        const float* Wl  = W_h + l * UN * UN;
        const float* bhl = b_h + l * UN;

        // stage chunk 0
        *(float4*)(WS + tid * 4)        = *(const float4*)(Wl + tid * 4);
        *(float4*)(WS + 1024 + tid * 4) = *(const float4*)(Wl + 1024 + tid * 4);
        zero_acc(acc);
        __syncthreads();

        // GEMM1: Ys[n][u] = relu(sum_c Xs[c][n] * W[c][u] + b[u]), W double-buffered
#pragma unroll 1
        for (int c = 0; c < 8; ++c) {
            float4 p0, p1;
            if (c < 7) {
                p0 = *(const float4*)(Wl + (c + 1) * 2048 + tid * 4);
                p1 = *(const float4*)(Wl + (c + 1) * 2048 + 1024 + tid * 4);
            }
            const float* wsb = WS + (c & 1) * 2048;
            const float* xk  = Xs + c * 16 * RL;
#pragma unroll 8
            for (int kk = 0; kk < 16; ++kk)
                mk_step(xk, RL, wsb, UN, kk, i0, j0, acc);
            if (c < 7) {
                *(float4*)(WS + ((c + 1) & 1) * 2048 + tid * 4)        = p0;
                *(float4*)(WS + ((c + 1) & 1) * 2048 + 1024 + tid * 4) = p1;
                __syncthreads();
            }
        }
        {
            float4 bj0 = *(const float4*)(bhl + j0);
            float4 bj1 = *(const float4*)(bhl + j0 + 4);
#pragma unroll
            for (int ii = 0; ii < 8; ++ii) {
                float2 q0 = unpack2(acc[ii][0]);
                float2 q1 = unpack2(acc[ii][1]);
                float2 q2 = unpack2(acc[ii][2]);
                float2 q3 = unpack2(acc[ii][3]);
                float4 r0 = make_float4(fmaxf(q0.x + bj0.x, 0.f), fmaxf(q0.y + bj0.y, 0.f),
                                        fmaxf(q1.x + bj0.z, 0.f), fmaxf(q1.y + bj0.w, 0.f));
                float4 r1 = make_float4(fmaxf(q2.x + bj1.x, 0.f), fmaxf(q2.y + bj1.y, 0.f),
                                        fmaxf(q3.x + bj1.z, 0.f), fmaxf(q3.y + bj1.w, 0.f));
                *(float4*)(Ys + (i0 + ii) * RL + j0)     = r0;
                *(float4*)(Ys + (i0 + ii) * RL + j0 + 4) = r1;
            }
        }
        __syncthreads();

        // GEMM2: Xs[u][i] = sum_n Ys[n][u] * AD[n][i]
        zero_acc(acc);
#pragma unroll 8
        for (int k = 0; k < NP; ++k)
            mk_step(Ys, RL, AD, RL, k, i0, j0, acc);
#pragma unroll
        for (int ii = 0; ii < 8; ++ii) {
            float2 q0 = unpack2(acc[ii][0]);
            float2 q1 = unpack2(acc[ii][1]);
            float2 q2 = unpack2(acc[ii][2]);
            float2 q3 = unpack2(acc[ii][3]);
            *(float4*)(Xs + (i0 + ii) * RL + j0)     = make_float4(q0.x, q0.y, q1.x, q1.y);
            *(float4*)(Xs + (i0 + ii) * RL + j0 + 4) = make_float4(q2.x, q2.y, q3.x, q3.y);
        }
        __syncthreads();
    }

    // ---------- Masked mean pool + output projection ----------
    {
        int u = tid & 127;
        int h = tid >> 7;
        float s = 0.f;
#pragma unroll 8
        for (int i2 = 0; i2 < 64; ++i2) {
            int i = h * 64 + i2;
            s += Xs[u * RL + i] * MSK[i];
        }
        Ys[h * 128 + u] = s;   // Ys reused as scratch
    }
    __syncthreads();
    if (tid < 128) {
        float pooled = (Ys[tid] + Ys[128 + tid]) / RED[7];
        float v = pooled * W_out[tid];
#pragma unroll
        for (int o = 16; o; o >>= 1) v += __shfl_down_sync(0xffffffffu, v, o);
        if ((tid & 31) == 0) RED[tid >> 5] = v;
    }
    __syncthreads();
    if (tid == 0) out[b] = RED[0] + RED[1] + RED[2] + RED[3] + b_out[0];
}

extern "C" void kernel_launch(void* const* d_in, const int* in_sizes, int n_in,
                              void* d_out, int out_size)
{
    const int*   pdg   = (const int*)  d_in[0];
    const float* feat  = (const float*)d_in[1];
    const float* adjp  = (const float*)d_in[2];
    const float* maskp = (const float*)d_in[3];
    const float* emb   = (const float*)d_in[4];
    const float* W_in  = (const float*)d_in[5];
    const float* b_in  = (const float*)d_in[6];
    const float* W_h   = (const float*)d_in[7];
    const float* b_h   = (const float*)d_in[8];
    const float* W_out = (const float*)d_in[9];
    const float* b_out = (const float*)d_in[10];
    float* out = (float*)d_out;

    const int B = in_sizes[0] / NP;   // pdg has B*N elements

    cudaFuncSetAttribute(gcn_fused_kernel,
                         cudaFuncAttributeMaxDynamicSharedMemorySize, SMEM_BYTES);
    gcn_fused_kernel<<<B, NTHREADS, SMEM_BYTES>>>(
        pdg, feat, adjp, maskp, emb, W_in, b_in, W_h, b_h, W_out, b_out, out);
}

// round 4
// speedup vs baseline: 1.1292x; 1.1292x over previous
#include <cuda_runtime.h>

#define RL  132     // padded smem row length (floats)
#define NP  128     // particles per event
#define UN  128     // hidden units
#define NHID 6
#define NTHREADS 512

// smem layout (floats):
//   Xs  [128][RL]  : xT (unit-major activations)   (also transpose staging early)
//   Ys  [128][RL]  : y  (particle-major dense out) (also x0T early, partials late)
//   AD  [128][RL]  : adjT  (AD[n][i] = adj[i][n])
//   WS  [2][16][128] : W chunk double buffer
//   MSK [128], RED[8] (RED[7] = denom)
#define SMEM_FLOATS (3 * NP * RL + 2 * 16 * UN + NP + 8)
#define SMEM_BYTES  (SMEM_FLOATS * 4)

__device__ __forceinline__ unsigned long long ffma2(unsigned long long a,
                                                    unsigned long long b,
                                                    unsigned long long c) {
    unsigned long long d;
    asm("fma.rn.f32x2 %0, %1, %2, %3;" : "=l"(d) : "l"(a), "l"(b), "l"(c));
    return d;
}

__device__ __forceinline__ unsigned long long pack2(float x) {
    unsigned long long d;
    asm("mov.b64 %0, {%1, %1};" : "=l"(d) : "f"(x));
    return d;
}

__device__ __forceinline__ float2 unpack2(unsigned long long v) {
    float2 f;
    asm("mov.b64 {%0, %1}, %2;" : "=f"(f.x), "=f"(f.y) : "l"(v));
    return f;
}

// One k-step of the 8i x 4j per-thread microkernel.
// C[i][j] += As[k][i] * Bs[k][j]
// A loaded as natural f32x2 pairs along i (no pack), B scalars packed (4 movs).
// acc[jj][p]: jj = j0+jj, p = i-pair (i0+2p, i0+2p+1)
__device__ __forceinline__ void mk_step(const float* __restrict__ As, int as,
                                        const float* __restrict__ Bs, int bs,
                                        int k, int i0, int j0,
                                        unsigned long long acc[4][4]) {
    ulonglong2 aq0 = *(const ulonglong2*)(As + k * as + i0);
    ulonglong2 aq1 = *(const ulonglong2*)(As + k * as + i0 + 4);
    float4 bv = *(const float4*)(Bs + k * bs + j0);
    unsigned long long ap[4] = {aq0.x, aq0.y, aq1.x, aq1.y};
    float bsc[4] = {bv.x, bv.y, bv.z, bv.w};
#pragma unroll
    for (int jj = 0; jj < 4; ++jj) {
        unsigned long long bp = pack2(bsc[jj]);
#pragma unroll
        for (int p = 0; p < 4; ++p) acc[jj][p] = ffma2(ap[p], bp, acc[jj][p]);
    }
}

__device__ __forceinline__ void zero_acc(unsigned long long acc[4][4]) {
#pragma unroll
    for (int jj = 0; jj < 4; ++jj)
#pragma unroll
        for (int p = 0; p < 4; ++p) acc[jj][p] = 0ull;
}

__global__ __launch_bounds__(NTHREADS, 1)
void gcn_fused_kernel(const int* __restrict__ pdg,
                      const float* __restrict__ feat,
                      const float* __restrict__ adj,
                      const float* __restrict__ mask,
                      const float* __restrict__ emb,
                      const float* __restrict__ W_in,
                      const float* __restrict__ b_in,
                      const float* __restrict__ W_h,
                      const float* __restrict__ b_h,
                      const float* __restrict__ W_out,
                      const float* __restrict__ b_out,
                      float* __restrict__ out)
{
    extern __shared__ float sm[];
    float* Xs  = sm;
    float* Ys  = Xs + NP * RL;
    float* AD  = Ys + NP * RL;
    float* WS  = AD + NP * RL;          // 2 * 16 * 128 floats
    float* MSK = WS + 2 * 16 * UN;      // 128
    float* RED = MSK + NP;              // 8 (RED[7] = denom)

    const int b    = blockIdx.x;
    const int tid  = threadIdx.x;
    const int lane = tid & 31;
    const int warp = tid >> 5;          // 0..15

    // 16 warps in 4x4 grid, each warp covers 32i x 32j.
    // within warp: 4 ty x 8 tx; per-thread tile 8i x 4j.
    const int warpY = warp >> 2;                 // 0..3
    const int warpX = warp & 3;                  // 0..3
    const int ty = lane >> 3;                    // 0..3
    const int tx = lane & 7;                     // 0..7
    const int i0 = (warpY * 4 + ty) * 8;         // 0..120 step 8
    const int j0 = (warpX * 8 + tx) * 4;         // 0..124 step 4

    const float* adjb = adj + (size_t)b * NP * NP;

    // ---------- Phase A: transpose adj into AD (AD[n][i] = adj[i][n]) ----------
    {
        float* stg = Xs + warp * (32 * 33);   // per-warp 32x33 staging (16*1056 = 16896 fits Xs)
        int ti = warp >> 2, tj = warp & 3;    // one 32x32 tile per warp
        // fill: coalesced global float4 read, SCALAR smem stores
#pragma unroll
        for (int s = 0; s < 8; ++s) {
            int r  = s * 4 + (lane >> 3);
            int c4 = lane & 7;
            float4 v = *(const float4*)(adjb + (ti * 32 + r) * NP + tj * 32 + c4 * 4);
            float* d = stg + r * 33 + c4 * 4;
            d[0] = v.x; d[1] = v.y; d[2] = v.z; d[3] = v.w;
        }
        __syncwarp();
        // drain transposed: conflict-free (33-pad) LDS + scalar STS
#pragma unroll
        for (int n2 = 0; n2 < 32; ++n2) {
            AD[(tj * 32 + n2) * RL + ti * 32 + lane] = stg[lane * 33 + n2];
        }
        __syncwarp();
    }

    // ---------- Phase B: x0T into Ys, W_in into WS, mask ----------
    if (tid < 128) {
        int n = tid;
        float4 f0 = *(const float4*)(feat + ((size_t)b * NP + n) * 8);
        float4 f1 = *(const float4*)(feat + ((size_t)b * NP + n) * 8 + 4);
        Ys[0 * RL + n] = f0.x; Ys[1 * RL + n] = f0.y;
        Ys[2 * RL + n] = f0.z; Ys[3 * RL + n] = f0.w;
        Ys[4 * RL + n] = f1.x; Ys[5 * RL + n] = f1.y;
        Ys[6 * RL + n] = f1.z; Ys[7 * RL + n] = f1.w;
        MSK[n] = mask[(size_t)b * NP + n];
    } else if (tid < 256) {
        int n = tid - 128;
        int p = pdg[(size_t)b * NP + n];
        float4 e0 = *(const float4*)(emb + p * 8);
        float4 e1 = *(const float4*)(emb + p * 8 + 4);
        Ys[ 8 * RL + n] = e0.x; Ys[ 9 * RL + n] = e0.y;
        Ys[10 * RL + n] = e0.z; Ys[11 * RL + n] = e0.w;
        Ys[12 * RL + n] = e1.x; Ys[13 * RL + n] = e1.y;
        Ys[14 * RL + n] = e1.z; Ys[15 * RL + n] = e1.w;
    }
    // W_in (16x128 = 2048 floats) into WS buf0: one float4 per thread
    *(float4*)(WS + tid * 4) = *(const float4*)(W_in + tid * 4);
    __syncthreads();

    // denom = max(sum(mask), 1)  (warp 0)
    if (warp == 0) {
        float s = MSK[lane] + MSK[lane + 32] + MSK[lane + 64] + MSK[lane + 96];
#pragma unroll
        for (int o = 16; o; o >>= 1) s += __shfl_down_sync(0xffffffffu, s, o);
        if (lane == 0) RED[7] = fmaxf(s, 1.0f);
    }

    unsigned long long acc[4][4];

    // ---------- Input GEMM: Xs[u][n] = sum_c W_in[c][u] * x0T[c][n] + b_in[u] ----------
    // C[i=u][j=n], A=WS, B=Ys(x0T), bias over i.
    zero_acc(acc);
#pragma unroll 8
    for (int k = 0; k < 16; ++k)
        mk_step(WS, UN, Ys, RL, k, i0, j0, acc);
    {
        float4 bi0 = *(const float4*)(b_in + i0);
        float4 bi1 = *(const float4*)(b_in + i0 + 4);
        float bia[8] = {bi0.x, bi0.y, bi0.z, bi0.w, bi1.x, bi1.y, bi1.z, bi1.w};
#pragma unroll
        for (int p = 0; p < 4; ++p) {
            float2 q0 = unpack2(acc[0][p]);
            float2 q1 = unpack2(acc[1][p]);
            float2 q2 = unpack2(acc[2][p]);
            float2 q3 = unpack2(acc[3][p]);
            float bl = bia[2 * p], bh = bia[2 * p + 1];
            *(float4*)(Xs + (i0 + 2 * p)     * RL + j0) = make_float4(q0.x + bl, q1.x + bl, q2.x + bl, q3.x + bl);
            *(float4*)(Xs + (i0 + 2 * p + 1) * RL + j0) = make_float4(q0.y + bh, q1.y + bh, q2.y + bh, q3.y + bh);
        }
    }
    __syncthreads();

    // ---------- Hidden layers ----------
#pragma unroll 1
    for (int l = 0; l < NHID; ++l) {
        const float* Wl  = W_h + l * UN * UN;
        const float* bhl = b_h + l * UN;

        // stage chunk 0 (2048 floats, one float4 per thread)
        *(float4*)(WS + tid * 4) = *(const float4*)(Wl + tid * 4);
        zero_acc(acc);
        __syncthreads();

        // GEMM1: Ys[n][u] = relu(sum_c Xs[c][n] * W[c][u] + b[u])
        // C[i=n][j=u], A=Xs(xT), B=WS, bias over j. W double-buffered.
#pragma unroll 1
        for (int c = 0; c < 8; ++c) {
            float4 p0;
            if (c < 7) p0 = *(const float4*)(Wl + (c + 1) * 2048 + tid * 4);
            const float* wsb = WS + (c & 1) * 2048;
            const float* xk  = Xs + c * 16 * RL;
#pragma unroll 8
            for (int kk = 0; kk < 16; ++kk)
                mk_step(xk, RL, wsb, UN, kk, i0, j0, acc);
            if (c < 7) {
                *(float4*)(WS + ((c + 1) & 1) * 2048 + tid * 4) = p0;
                __syncthreads();
            }
        }
        {
            float4 bj = *(const float4*)(bhl + j0);
#pragma unroll
            for (int p = 0; p < 4; ++p) {
                float2 q0 = unpack2(acc[0][p]);
                float2 q1 = unpack2(acc[1][p]);
                float2 q2 = unpack2(acc[2][p]);
                float2 q3 = unpack2(acc[3][p]);
                *(float4*)(Ys + (i0 + 2 * p) * RL + j0) =
                    make_float4(fmaxf(q0.x + bj.x, 0.f), fmaxf(q1.x + bj.y, 0.f),
                                fmaxf(q2.x + bj.z, 0.f), fmaxf(q3.x + bj.w, 0.f));
                *(float4*)(Ys + (i0 + 2 * p + 1) * RL + j0) =
                    make_float4(fmaxf(q0.y + bj.x, 0.f), fmaxf(q1.y + bj.y, 0.f),
                                fmaxf(q2.y + bj.z, 0.f), fmaxf(q3.y + bj.w, 0.f));
            }
        }
        __syncthreads();

        // GEMM2: Xs[u][i] = sum_n Ys[n][u] * AD[n][i]
        // C[i=u][j=particle], A=Ys, B=AD.
        zero_acc(acc);
#pragma unroll 8
        for (int k = 0; k < NP; ++k)
            mk_step(Ys, RL, AD, RL, k, i0, j0, acc);
#pragma unroll
        for (int p = 0; p < 4; ++p) {
            float2 q0 = unpack2(acc[0][p]);
            float2 q1 = unpack2(acc[1][p]);
            float2 q2 = unpack2(acc[2][p]);
            float2 q3 = unpack2(acc[3][p]);
            *(float4*)(Xs + (i0 + 2 * p)     * RL + j0) = make_float4(q0.x, q1.x, q2.x, q3.x);
            *(float4*)(Xs + (i0 + 2 * p + 1) * RL + j0) = make_float4(q0.y, q1.y, q2.y, q3.y);
        }
        __syncthreads();
    }

    // ---------- Masked mean pool + output projection ----------
    {
        int u = tid & 127;
        int h = tid >> 7;          // 0..3
        float s = 0.f;
#pragma unroll 8
        for (int i2 = 0; i2 < 32; ++i2) {
            int i = h * 32 + i2;
            s += Xs[u * RL + i] * MSK[i];
        }
        Ys[h * 128 + u] = s;       // Ys reused as scratch (512 floats)
    }
    __syncthreads();
    if (tid < 128) {
        float pooled = (Ys[tid] + Ys[128 + tid] + Ys[256 + tid] + Ys[384 + tid]) / RED[7];
        float v = pooled * W_out[tid];
#pragma unroll
        for (int o = 16; o; o >>= 1) v += __shfl_down_sync(0xffffffffu, v, o);
        if ((tid & 31) == 0) RED[tid >> 5] = v;
    }
    __syncthreads();
    if (tid == 0) out[b] = RED[0] + RED[1] + RED[2] + RED[3] + b_out[0];
}

extern "C" void kernel_launch(void* const* d_in, const int* in_sizes, int n_in,
                              void* d_out, int out_size)
{
    const int*   pdg   = (const int*)  d_in[0];
    const float* feat  = (const float*)d_in[1];
    const float* adjp  = (const float*)d_in[2];
    const float* maskp = (const float*)d_in[3];
    const float* emb   = (const float*)d_in[4];
    const float* W_in  = (const float*)d_in[5];
    const float* b_in  = (const float*)d_in[6];
    const float* W_h   = (const float*)d_in[7];
    const float* b_h   = (const float*)d_in[8];
    const float* W_out = (const float*)d_in[9];
    const float* b_out = (const float*)d_in[10];
    float* out = (float*)d_out;

    const int B = in_sizes[0] / NP;   // pdg has B*N elements

    cudaFuncSetAttribute(gcn_fused_kernel,
                         cudaFuncAttributeMaxDynamicSharedMemorySize, SMEM_BYTES);
    gcn_fused_kernel<<<B, NTHREADS, SMEM_BYTES>>>(
        pdg, feat, adjp, maskp, emb, W_in, b_in, W_h, b_h, W_out, b_out, out);
}